// round 4
// baseline (speedup 1.0000x reference)
#include <cuda_runtime.h>
#include <math.h>

// Problem constants (fixed by the reference):
#define NCLASS   4096   // C: number of classes == logit dim
#define NROWS    8192   // N: number of samples
#define ROWLEN   4096   // feature length per row (== C)
#define NUM_POS  4

// final scale = NUM_POS / (N*N) = 4 / (8192*8192)
#define LOSS_SCALE (4.0f / (8192.0f * 8192.0f))

// Scratch (no allocations allowed -> __device__ globals)
__device__ int g_count[NCLASS];
__device__ int g_offset[NCLASS];
__device__ int g_rows[NROWS];

// ---------------------------------------------------------------------------
// Kernel 1: single-CTA CSR build over labels + zero the output.
//   - Detects whether the label buffer is int32 or int64 (jax x64 ambiguity):
//     viewed as int32, an int64 little-endian buffer has all odd words == 0
//     (labels < 4096 << 2^31). An int32 buffer has random labels at odd words.
//   - Shared-memory histogram, parallel exclusive scan (4096), scatter.
// ---------------------------------------------------------------------------
__global__ void __launch_bounds__(1024) build_csr_kernel(
    const int* __restrict__ label32, float* __restrict__ out, int out_size)
{
    __shared__ int s_count[NCLASS];    // 16 KB
    __shared__ int s_cursor[NCLASS];   // 16 KB
    __shared__ int s_warp[32];
    __shared__ int s_flag;

    const int tid = threadIdx.x;            // 1024 threads
    if (tid == 0) s_flag = 0;
    for (int i = tid; i < NCLASS; i += 1024) s_count[i] = 0;
    __syncthreads();

    // --- layout detection: scan odd int32 words among first NROWS words ---
    int any = 0;
    for (int i = tid; i < NROWS / 2; i += 1024)
        any |= label32[2 * i + 1];
    if (any) atomicOr(&s_flag, 1);
    __syncthreads();
    const int stride = s_flag ? 1 : 2;      // 1: int32 labels, 2: int64 labels

    // --- histogram ---
    for (int i = tid; i < NROWS; i += 1024) {
        int c = label32[i * stride];
        atomicAdd(&s_count[c], 1);
    }
    __syncthreads();

    // --- exclusive scan of 4096 counts (4 per thread) ---
    const int lane = tid & 31, wid = tid >> 5;
    int c0 = s_count[4 * tid + 0];
    int c1 = s_count[4 * tid + 1];
    int c2 = s_count[4 * tid + 2];
    int c3 = s_count[4 * tid + 3];
    int local = c0 + c1 + c2 + c3;

    int incl = local;
    #pragma unroll
    for (int o = 1; o < 32; o <<= 1) {
        int y = __shfl_up_sync(0xffffffffu, incl, o);
        if (lane >= o) incl += y;
    }
    int excl_in_warp = incl - local;
    if (lane == 31) s_warp[wid] = incl;     // warp totals
    __syncthreads();
    if (tid < 32) {
        int w = s_warp[tid];
        int xw = w;
        #pragma unroll
        for (int o = 1; o < 32; o <<= 1) {
            int y = __shfl_up_sync(0xffffffffu, xw, o);
            if (tid >= o) xw += y;
        }
        s_warp[tid] = xw - w;               // exclusive warp base
    }
    __syncthreads();

    int base = s_warp[wid] + excl_in_warp;
    int o0 = base;
    int o1 = base + c0;
    int o2 = base + c0 + c1;
    int o3 = base + c0 + c1 + c2;

    g_count[4 * tid + 0] = c0;  g_offset[4 * tid + 0] = o0;  s_cursor[4 * tid + 0] = o0;
    g_count[4 * tid + 1] = c1;  g_offset[4 * tid + 1] = o1;  s_cursor[4 * tid + 1] = o1;
    g_count[4 * tid + 2] = c2;  g_offset[4 * tid + 2] = o2;  s_cursor[4 * tid + 2] = o2;
    g_count[4 * tid + 3] = c3;  g_offset[4 * tid + 3] = o3;  s_cursor[4 * tid + 3] = o3;
    __syncthreads();

    // --- scatter row indices per class ---
    for (int i = tid; i < NROWS; i += 1024) {
        int c = label32[i * stride];
        int pos = atomicAdd(&s_cursor[c], 1);
        g_rows[pos] = i;
    }

    // --- zero output (poisoned by harness) ---
    for (int i = tid; i < out_size; i += 1024) out[i] = 0.0f;
}

// ---------------------------------------------------------------------------
// Kernel 2: one CTA per class.
//   Sum count[c] feat rows (float4 streaming, each row read exactly once
//   chip-wide -> 128 MB total), scale by 1/count, block lse, pick column c,
//   atomicAdd weighted loss into out[0].
// ---------------------------------------------------------------------------
__global__ void __launch_bounds__(256) class_loss_kernel(
    const float* __restrict__ feat, float* __restrict__ out)
{
    const int c   = blockIdx.x;
    const int cnt = g_count[c];
    if (cnt == 0) return;
    const int off = g_offset[c];
    const int t   = threadIdx.x;            // 256 threads

    float4 a0 = make_float4(0.f, 0.f, 0.f, 0.f);
    float4 a1 = a0, a2 = a0, a3 = a0;

    for (int r = 0; r < cnt; ++r) {
        const float4* row =
            (const float4*)(feat + (size_t)g_rows[off + r] * ROWLEN);
        float4 l0 = __ldg(&row[t +   0]);
        float4 l1 = __ldg(&row[t + 256]);
        float4 l2 = __ldg(&row[t + 512]);
        float4 l3 = __ldg(&row[t + 768]);
        a0.x += l0.x; a0.y += l0.y; a0.z += l0.z; a0.w += l0.w;
        a1.x += l1.x; a1.y += l1.y; a1.z += l1.z; a1.w += l1.w;
        a2.x += l2.x; a2.y += l2.y; a2.z += l2.z; a2.w += l2.w;
        a3.x += l3.x; a3.y += l3.y; a3.z += l3.z; a3.w += l3.w;
    }

    const float inv = 1.0f / (float)cnt;
    float v[16];
    v[ 0] = a0.x * inv; v[ 1] = a0.y * inv; v[ 2] = a0.z * inv; v[ 3] = a0.w * inv;
    v[ 4] = a1.x * inv; v[ 5] = a1.y * inv; v[ 6] = a1.z * inv; v[ 7] = a1.w * inv;
    v[ 8] = a2.x * inv; v[ 9] = a2.y * inv; v[10] = a2.z * inv; v[11] = a2.w * inv;
    v[12] = a3.x * inv; v[13] = a3.y * inv; v[14] = a3.z * inv; v[15] = a3.w * inv;

    __shared__ float s_redA[8];
    __shared__ float s_redB[8];
    __shared__ float s_xc;

    // stash x_c: element index of v[j*4+comp] is (t + j*256)*4 + comp
    {
        int tc = (c >> 2) & 255;
        if (t == tc) {
            int j    = (c >> 2) >> 8;
            int comp = c & 3;
            s_xc = v[j * 4 + comp];
        }
    }

    // --- block max ---
    float m = v[0];
    #pragma unroll
    for (int k = 1; k < 16; ++k) m = fmaxf(m, v[k]);
    #pragma unroll
    for (int o = 16; o > 0; o >>= 1)
        m = fmaxf(m, __shfl_xor_sync(0xffffffffu, m, o));
    if ((t & 31) == 0) s_redA[t >> 5] = m;
    __syncthreads();
    if (t < 8) {
        float mm = s_redA[t];
        #pragma unroll
        for (int o = 4; o > 0; o >>= 1)
            mm = fmaxf(mm, __shfl_xor_sync(0xffu, mm, o));
        if (t == 0) s_redA[0] = mm;
    }
    __syncthreads();
    const float M = s_redA[0];

    // --- block sum of exp(v - M) ---
    float s = 0.0f;
    #pragma unroll
    for (int k = 0; k < 16; ++k) s += expf(v[k] - M);
    #pragma unroll
    for (int o = 16; o > 0; o >>= 1)
        s += __shfl_xor_sync(0xffffffffu, s, o);
    if ((t & 31) == 0) s_redB[t >> 5] = s;
    __syncthreads();
    if (t == 0) {
        float S = 0.0f;
        #pragma unroll
        for (int k = 0; k < 8; ++k) S += s_redB[k];
        float lse  = M + logf(S);
        float loss = (float)cnt * (lse - s_xc);
        atomicAdd(out, loss * LOSS_SCALE);
    }
}

// ---------------------------------------------------------------------------
extern "C" void kernel_launch(void* const* d_in, const int* in_sizes, int n_in,
                              void* d_out, int out_size)
{
    const float* feat    = (const float*)d_in[0];
    const int*   label32 = (const int*)d_in[1];   // int32 view; layout probed
    float*       out     = (float*)d_out;

    build_csr_kernel<<<1, 1024>>>(label32, out, out_size);
    class_loss_kernel<<<NCLASS, 256>>>(feat, out);
}